// round 6
// baseline (speedup 1.0000x reference)
#include <cuda_runtime.h>
#include <cuda_bf16.h>
#include <stdint.h>

// x: (B=8, C=3, H=1024, W=1024) fp32; patch=24, stride=16, reflect m=4
// out: (8*64*64, 576, 3) fp32 = 56,623,104 elems (+ maybe (nH,nW)).
#define PATCH_ELEMS 56623104u
#define NTILES 2048u          // 8 images x 16 x 16 tiles of 4x4 patches
#define THREADS 288u

#define SW 76u                 // smem row width in floats (72 data + 4 pad)
#define SROWS 72u              // 64 + 2*4 halo
#define PLANE_STRIDE (SROWS * SW)          // 5472 floats
#define SMEM_FLOATS (3u * PLANE_STRIDE)    // 16416 floats
#define SMEM_BYTES (SMEM_FLOATS * 4u)      // 65664 B

__device__ __forceinline__ int reflect1024(int v) {
    v = (v < 0) ? -v : v;                 // jnp 'reflect' (no edge repeat)
    v = (v >= 1024) ? (2046 - v) : v;
    return v;
}

__global__ __launch_bounds__(THREADS)
void Patcher_78280073937146_kernel(const float* __restrict__ x,
                                   float* __restrict__ out,
                                   unsigned out_elems) {
    unsigned bid = blockIdx.x;
    unsigned t = threadIdx.x;

    if (bid >= NTILES) {
        // trailing (nH, nW) = (64, 64) slots, if the harness appends them
        unsigned e = PATCH_ELEMS + (bid - NTILES) * THREADS + t;
        if (e < out_elems) out[e] = 64.0f;
        return;
    }

    extern __shared__ float sm[];

    unsigned b  = bid >> 8;          // image
    unsigned ty = (bid >> 4) & 15u;  // tile row (4 patches each)
    unsigned tx = bid & 15u;         // tile col
    int oy = (int)(ty << 6) - 4;     // smem origin in image coords
    int ox = (int)(tx << 6) - 4;

    // ---- stage input tile: 3 planes x 72 rows x 72 cols (18 float4/row) ----
    bool edge = (tx == 0u) || (tx == 15u);
    for (unsigned v = t; v < 3888u; v += THREADS) {
        unsigned plane = v / 1296u;
        unsigned rem   = v - plane * 1296u;
        unsigned row   = rem / 18u;
        unsigned i4    = rem - row * 18u;
        int gy = reflect1024(oy + (int)row);
        unsigned gbase = ((b * 3u + plane) << 20) + (((unsigned)gy) << 10);
        int c0 = ox + (int)(i4 << 2);          // 16B-aligned (ox ≡ -4 mod 16)
        float4 vv;
        if (!edge) {
            vv = *reinterpret_cast<const float4*>(x + gbase + (unsigned)c0);
        } else {
            float tv[4];
            #pragma unroll
            for (int kk = 0; kk < 4; ++kk)
                tv[kk] = x[gbase + (unsigned)reflect1024(c0 + kk)];
            vv = make_float4(tv[0], tv[1], tv[2], tv[3]);
        }
        *reinterpret_cast<float4*>(&sm[plane * PLANE_STRIDE + row * SW + (i4 << 2)]) = vv;
    }
    __syncthreads();

    // ---- emit: 1152 octets (8 px x 3 ch) per tile, 4 per thread ----
    unsigned patchBaseG = (b << 12) + (ty << 2) * 64u + (tx << 2);
    #pragma unroll
    for (unsigned k = 0; k < 4u; ++k) {
        unsigned o       = t + k * THREADS;     // 0..1151
        unsigned patch_l = o / 72u;             // 0..15
        unsigned rem     = o - patch_l * 72u;
        unsigned iu      = rem / 3u;            // patch row 0..23
        unsigned p       = rem - iu * 3u;       // octet 0..2
        unsigned ph_l = patch_l >> 2, pw_l = patch_l & 3u;
        unsigned lr = (ph_l << 4) + iu;         // 0..71
        unsigned lc = (pw_l << 4) + (p << 3);   // 0..64, 8-float aligned

        const float* s0 = &sm[lr * SW + lc];
        float4 r0l = *reinterpret_cast<const float4*>(s0);
        float4 r0h = *reinterpret_cast<const float4*>(s0 + 4);
        float4 r1l = *reinterpret_cast<const float4*>(s0 + PLANE_STRIDE);
        float4 r1h = *reinterpret_cast<const float4*>(s0 + PLANE_STRIDE + 4);
        float4 r2l = *reinterpret_cast<const float4*>(s0 + 2u * PLANE_STRIDE);
        float4 r2h = *reinterpret_cast<const float4*>(s0 + 2u * PLANE_STRIDE + 4);

        float4 o0 = make_float4(r0l.x, r1l.x, r2l.x, r0l.y);
        float4 o1 = make_float4(r1l.y, r2l.y, r0l.z, r1l.z);
        float4 o2 = make_float4(r2l.z, r0l.w, r1l.w, r2l.w);
        float4 o3 = make_float4(r0h.x, r1h.x, r2h.x, r0h.y);
        float4 o4 = make_float4(r1h.y, r2h.y, r0h.z, r1h.z);
        float4 o5 = make_float4(r2h.z, r0h.w, r1h.w, r2h.w);

        unsigned patchG = patchBaseG + (ph_l << 6) + pw_l;
        float4* ov = reinterpret_cast<float4*>(out)
                   + (size_t)patchG * 432u + iu * 18u + p * 6u;
        __stcs(ov + 0, o0);
        __stcs(ov + 1, o1);
        __stcs(ov + 2, o2);
        __stcs(ov + 3, o3);
        __stcs(ov + 4, o4);
        __stcs(ov + 5, o5);
    }
}

extern "C" void kernel_launch(void* const* d_in, const int* in_sizes, int n_in,
                              void* d_out, int out_size) {
    const float* x = (const float*)d_in[0];
    float* out = (float*)d_out;
    unsigned out_elems = (unsigned)out_size;

    cudaFuncSetAttribute(Patcher_78280073937146_kernel,
                         cudaFuncAttributeMaxDynamicSharedMemorySize, SMEM_BYTES);

    unsigned extraElems  = (out_elems > PATCH_ELEMS) ? (out_elems - PATCH_ELEMS) : 0u;
    unsigned extraBlocks = (extraElems + THREADS - 1u) / THREADS;
    Patcher_78280073937146_kernel<<<NTILES + extraBlocks, THREADS, SMEM_BYTES>>>(
        x, out, out_elems);
}

// round 7
// speedup vs baseline: 1.4319x; 1.4319x over previous
#include <cuda_runtime.h>
#include <cuda_bf16.h>
#include <stdint.h>

// x: (B=8, C=3, H=1024, W=1024) fp32; patch=24, stride=16, reflect m=4
// out: (8*64*64, 576, 3) fp32 = 56,623,104 elems (+ maybe (nH,nW)=(64,64)).
#define PATCH_ELEMS 56623104u
#define TOTAL_QUADS 4718592u
#define HALF_QUADS  2359296u   // thread handles quad g and g+HALF (image b and b+4)

__device__ __forceinline__ int reflect1024(int v) {
    v = (v < 0) ? -v : v;                 // jnp 'reflect' (no edge repeat)
    v = (v >= 1024) ? (2046 - v) : v;
    return v;
}

__global__ __launch_bounds__(256, 6)
void Patcher_78280073937146_kernel(const float* __restrict__ x,
                                   float* __restrict__ out,
                                   unsigned out_elems) {
    unsigned g = blockIdx.x * 256u + threadIdx.x;

    if (g < HALF_QUADS) {
        // ---- one decode serves BOTH quads: g (images 0..3) and g+HALF (b+4) ----
        unsigned patch = g / 144u;            // 0..16383
        unsigned u     = g - patch * 144u;    // 0..143
        unsigned iu    = u / 6u;              // patch row 0..23
        unsigned jq    = u - iu * 6u;         // col-quad 0..5

        unsigned b  = patch >> 12;            // 0..3
        unsigned ph = (patch >> 6) & 63u;
        unsigned pw = patch & 63u;

        int y  = reflect1024((int)(ph * 16u + iu) - 4);
        int x0 = (int)(pw * 16u + (jq << 2)) - 4;   // -4 .. 1020 (step 4)

        unsigned baseA = ((b * 3u) << 20) + (((unsigned)y) << 10);
        unsigned baseB = baseA + (12u << 20);       // image b+4, same row

        float4 a0, a1, a2, b0, b1, b2;              // 3 planes x 2 quads

        if ((unsigned)x0 <= 1020u) {
            // hot path: 6 independent front-batched LDG.128 (MLP=6)
            const float* pa = x + baseA + (unsigned)x0;
            const float* pb = x + baseB + (unsigned)x0;
            a0 = *reinterpret_cast<const float4*>(pa);
            a1 = *reinterpret_cast<const float4*>(pa + (1u << 20));
            a2 = *reinterpret_cast<const float4*>(pa + (2u << 20));
            b0 = *reinterpret_cast<const float4*>(pb);
            b1 = *reinterpret_cast<const float4*>(pb + (1u << 20));
            b2 = *reinterpret_cast<const float4*>(pb + (2u << 20));
        } else {
            // rare reflected edge (x0 == -4 or 1024): scalar, both quads
            float ta[3][4], tb[3][4];
            #pragma unroll
            for (int k = 0; k < 4; ++k) {
                unsigned xr = (unsigned)reflect1024(x0 + k);
                #pragma unroll
                for (int c = 0; c < 3; ++c) {
                    ta[c][k] = x[baseA + (((unsigned)c) << 20) + xr];
                    tb[c][k] = x[baseB + (((unsigned)c) << 20) + xr];
                }
            }
            a0 = make_float4(ta[0][0], ta[0][1], ta[0][2], ta[0][3]);
            a1 = make_float4(ta[1][0], ta[1][1], ta[1][2], ta[1][3]);
            a2 = make_float4(ta[2][0], ta[2][1], ta[2][2], ta[2][3]);
            b0 = make_float4(tb[0][0], tb[0][1], tb[0][2], tb[0][3]);
            b1 = make_float4(tb[1][0], tb[1][1], tb[1][2], tb[1][3]);
            b2 = make_float4(tb[2][0], tb[2][1], tb[2][2], tb[2][3]);
        }

        // ---- permute channel-planes -> (pixel, channel) interleave ----
        float4 oA0 = make_float4(a0.x, a1.x, a2.x, a0.y);
        float4 oA1 = make_float4(a1.y, a2.y, a0.z, a1.z);
        float4 oA2 = make_float4(a2.z, a0.w, a1.w, a2.w);
        float4 oB0 = make_float4(b0.x, b1.x, b2.x, b0.y);
        float4 oB1 = make_float4(b1.y, b2.y, b0.z, b1.z);
        float4 oB2 = make_float4(b2.z, b0.w, b1.w, b2.w);

        float4* ovA = reinterpret_cast<float4*>(out) + (size_t)g * 3u;
        float4* ovB = ovA + 7077888u;               // (+HALF_QUADS quads) * 3
        __stcs(ovA + 0, oA0);
        __stcs(ovA + 1, oA1);
        __stcs(ovA + 2, oA2);
        __stcs(ovB + 0, oB0);
        __stcs(ovB + 1, oB1);
        __stcs(ovB + 2, oB2);
    } else {
        // trailing (nH, nW) = (64, 64) slots, if the harness appends them
        unsigned e = PATCH_ELEMS + (g - HALF_QUADS);
        if (e < out_elems) out[e] = 64.0f;
    }
}

extern "C" void kernel_launch(void* const* d_in, const int* in_sizes, int n_in,
                              void* d_out, int out_size) {
    const float* x = (const float*)d_in[0];
    float* out = (float*)d_out;
    unsigned out_elems = (unsigned)out_size;

    unsigned mainBlocks  = HALF_QUADS / 256u;   // 9216 exact
    unsigned extraElems  = (out_elems > PATCH_ELEMS) ? (out_elems - PATCH_ELEMS) : 0u;
    unsigned extraBlocks = (extraElems + 255u) / 256u;
    Patcher_78280073937146_kernel<<<mainBlocks + extraBlocks, 256>>>(x, out, out_elems);
}